// round 13
// baseline (speedup 1.0000x reference)
#include <cuda_runtime.h>
#include <cstdint>

// Problem constants
#define Bn 8
#define Cc 512
#define Ww 14
#define HS 1024
#define Sp 196      // 14*14
#define KC 144      // 12*12 interior centers
#define On 9        // 3x3 offsets
#define NK 18       // 144 / 8 k-steps

// Scratch (__device__ globals: allocation-free rule)
__device__ float g_P1[Bn * HS * Sp];
__device__ float g_P2[Bn * HS * Sp];
__device__ float g_Ag[(size_t)Bn * HS * KC];          // gathered, tf32-rounded, k-permuted
__device__ float g_Bg[(size_t)Bn * On * HS * KC];     // gathered, tf32-rounded, k-permuted
__device__ float g_Gp[4 * (size_t)Bn * On * KC * KC]; // partial Gram matrices (4 j-quarters)
__device__ float g_scale[(size_t)Bn * On * HS];       // per-row 1/max(||row||,eps)

__device__ __forceinline__ void mma_tf32(float* c, uint32_t a0, uint32_t a1,
                                         uint32_t a2, uint32_t a3,
                                         uint32_t b0, uint32_t b1) {
    asm volatile(
        "mma.sync.aligned.m16n8k8.row.col.f32.tf32.tf32.f32 "
        "{%0,%1,%2,%3}, {%4,%5,%6,%7}, {%8,%9}, {%0,%1,%2,%3};"
        : "+f"(c[0]), "+f"(c[1]), "+f"(c[2]), "+f"(c[3])
        : "r"(a0), "r"(a1), "r"(a2), "r"(a3), "r"(b0), "r"(b1));
}

__device__ __forceinline__ uint32_t smem_u32(const void* p) {
    uint32_t a;
    asm("{ .reg .u64 t; cvta.to.shared.u64 t, %1; cvt.u32.u64 %0, t; }" : "=r"(a) : "l"(p));
    return a;
}
__device__ __forceinline__ void cp_async16(uint32_t dst, const void* src) {
    asm volatile("cp.async.ca.shared.global [%0], [%1], 16;" :: "r"(dst), "l"(src));
}
#define CP_COMMIT() asm volatile("cp.async.commit_group;" ::: "memory")
#define CP_WAIT(n)  asm volatile("cp.async.wait_group %0;" :: "n"(n) : "memory")

// ---------------------------------------------------------------------------
// proj: P[b][h][s] = sum_c w[h][c] * x[b][c][s] + bias[h]   (unchanged, passing)
// ---------------------------------------------------------------------------
__global__ __launch_bounds__(256) void proj_kernel(const float* __restrict__ x,
                                                   const float* __restrict__ w,
                                                   const float* __restrict__ bias,
                                                   int which)
{
    __shared__ __align__(16) float Wst[32 * 68];
    __shared__ __align__(16) float Xs[32 * 33];

    float* outP = which ? g_P2 : g_P1;
    const int tid = threadIdx.x;
    const int tx = tid & 15;
    const int ty = tid >> 4;
    const int sbase = blockIdx.x * 32;
    const int hbase = blockIdx.y * 64;
    const int b = blockIdx.z;

    float acc[4][2] = {};
    for (int cb = 0; cb < Cc; cb += 32) {
        #pragma unroll
        for (int r = 0; r < 8; ++r) {
            int l = tid + r * 256;
            int h = l >> 5, c = l & 31;
            Wst[c * 68 + h] = w[(hbase + h) * Cc + cb + c];
        }
        #pragma unroll
        for (int r = 0; r < 4; ++r) {
            int l = tid + r * 256;
            int c = l >> 5, s = l & 31;
            int sg = sbase + s;
            Xs[c * 33 + s] = (sg < Sp) ? x[(b * Cc + cb + c) * Sp + sg] : 0.f;
        }
        __syncthreads();
        #pragma unroll 8
        for (int c = 0; c < 32; ++c) {
            float4 a = *(const float4*)(Wst + c * 68 + ty * 4);
            float b0 = Xs[c * 33 + tx * 2];
            float b1 = Xs[c * 33 + tx * 2 + 1];
            acc[0][0] += a.x * b0; acc[0][1] += a.x * b1;
            acc[1][0] += a.y * b0; acc[1][1] += a.y * b1;
            acc[2][0] += a.z * b0; acc[2][1] += a.z * b1;
            acc[3][0] += a.w * b0; acc[3][1] += a.w * b1;
        }
        __syncthreads();
    }
    #pragma unroll
    for (int u = 0; u < 4; ++u) {
        int h = hbase + ty * 4 + u;
        float bb = bias[h];
        #pragma unroll
        for (int v = 0; v < 2; ++v) {
            int s = sbase + tx * 2 + v;
            if (s < Sp) outP[(b * HS + h) * Sp + s] = acc[u][v] + bb;
        }
    }
}

// ---------------------------------------------------------------------------
// gather: gathered operands, tf32-rounded, k-chunk permuted [0,4,1,5,2,6,3,7]
// ---------------------------------------------------------------------------
__global__ __launch_bounds__(160) void gather_kernel()
{
    int row = blockIdx.x;
    int k = threadIdx.x;
    if (k >= KC) return;
    int ky = k / 12, kx = k - ky * 12;
    int ks = k >> 3, kk = k & 7;
    int dpos = ks * 8 + (kk & 3) * 2 + (kk >> 2);
    float v;
    if (row < Bn * HS) {
        int s = (1 + ky) * Ww + 1 + kx;
        v = g_P1[(size_t)row * Sp + s];
        asm("cvt.rna.tf32.f32 %0, %0;" : "+f"(v));
        g_Ag[(size_t)row * KC + dpos] = v;
    } else {
        int r2 = row - Bn * HS;
        int b = r2 / (On * HS);
        int rem = r2 - b * On * HS;
        int o = rem >> 10;
        int j = rem & 1023;
        int delta = (o / 3 - 1) * Ww + (o % 3 - 1);
        int s = (1 + ky) * Ww + 1 + kx + delta;
        v = g_P2[((size_t)b * HS + j) * Sp + s];
        asm("cvt.rna.tf32.f32 %0, %0;" : "+f"(v));
        g_Bg[(size_t)r2 * KC + dpos] = v;
    }
}

// ---------------------------------------------------------------------------
// gram: partial Gram G_q = Bg_q^T Bg_q (144x144), per (b,o,quarter).
// CTA = (o, b, q), 288 threads = 9 warps (3m x 3n), warp tile 48x48.
// Each quarter covers 256 j in 4 chunks of 64, double-buffered.
// ---------------------------------------------------------------------------
#define TP 65
#define TBUF (KC * TP)
#define SMEM_GRAM (2 * TBUF * 4)   // 74880

__global__ __launch_bounds__(288, 1) void gram_kernel()
{
    extern __shared__ __align__(16) float T[];   // [2][KC*TP]

    const int tid = threadIdx.x;
    const int wid = tid >> 5;
    const int lane = tid & 31;
    const int gid = lane >> 2;
    const int tg = lane & 3;
    const int wm = wid / 3;
    const int wn = wid % 3;
    const int o = blockIdx.x;
    const int b = blockIdx.y;
    const int quarter = blockIdx.z;

    const float* Bb = g_Bg + ((size_t)(b * On + o) * HS + quarter * 256) * KC;

    int lj[8], lk4[8];
    #pragma unroll
    for (int r = 0; r < 8; ++r) {
        int l = tid + r * 288;
        lj[r] = l / 36;
        lk4[r] = l - lj[r] * 36;
    }

    float4 ld[8];
    #pragma unroll
    for (int r = 0; r < 8; ++r)
        ld[r] = *(const float4*)(Bb + (size_t)lj[r] * KC + lk4[r] * 4);
    #pragma unroll
    for (int r = 0; r < 8; ++r) {
        T[(4 * lk4[r] + 0) * TP + lj[r]] = ld[r].x;
        T[(4 * lk4[r] + 1) * TP + lj[r]] = ld[r].y;
        T[(4 * lk4[r] + 2) * TP + lj[r]] = ld[r].z;
        T[(4 * lk4[r] + 3) * TP + lj[r]] = ld[r].w;
    }
    __syncthreads();

    float acc[3][6][4] = {};

    for (int jc = 0; jc < 4; ++jc) {
        const float* cur = T + (jc & 1) * TBUF;
        float* nxt = T + ((jc & 1) ^ 1) * TBUF;

        if (jc < 3) {
            const float* Bc = Bb + (size_t)(jc + 1) * 64 * KC;
            #pragma unroll
            for (int r = 0; r < 8; ++r)
                ld[r] = *(const float4*)(Bc + (size_t)lj[r] * KC + lk4[r] * 4);
        }

        #pragma unroll
        for (int js = 0; js < 8; ++js) {
            int j0 = js * 8 + tg;
            uint32_t af[3][4], bf[6][2];
            #pragma unroll
            for (int mt = 0; mt < 3; ++mt) {
                int m = wm * 48 + mt * 16 + gid;
                af[mt][0] = __float_as_uint(cur[m * TP + j0]);
                af[mt][1] = __float_as_uint(cur[(m + 8) * TP + j0]);
                af[mt][2] = __float_as_uint(cur[m * TP + j0 + 4]);
                af[mt][3] = __float_as_uint(cur[(m + 8) * TP + j0 + 4]);
            }
            #pragma unroll
            for (int nt = 0; nt < 6; ++nt) {
                int n = wn * 48 + nt * 8 + gid;
                bf[nt][0] = __float_as_uint(cur[n * TP + j0]);
                bf[nt][1] = __float_as_uint(cur[n * TP + j0 + 4]);
            }
            #pragma unroll
            for (int mt = 0; mt < 3; ++mt)
                #pragma unroll
                for (int nt = 0; nt < 6; ++nt)
                    mma_tf32(acc[mt][nt], af[mt][0], af[mt][1], af[mt][2], af[mt][3],
                             bf[nt][0], bf[nt][1]);
        }

        if (jc < 3) {
            #pragma unroll
            for (int r = 0; r < 8; ++r) {
                nxt[(4 * lk4[r] + 0) * TP + lj[r]] = ld[r].x;
                nxt[(4 * lk4[r] + 1) * TP + lj[r]] = ld[r].y;
                nxt[(4 * lk4[r] + 2) * TP + lj[r]] = ld[r].z;
                nxt[(4 * lk4[r] + 3) * TP + lj[r]] = ld[r].w;
            }
        }
        __syncthreads();
    }

    float* Gp = g_Gp + ((size_t)quarter * Bn * On + (size_t)(b * On + o)) * KC * KC;
    #pragma unroll
    for (int mt = 0; mt < 3; ++mt) {
        int r = wm * 48 + mt * 16 + gid;
        #pragma unroll
        for (int nt = 0; nt < 6; ++nt) {
            int c = wn * 48 + nt * 8 + tg * 2;
            *(float2*)(Gp + r * KC + c) = make_float2(acc[mt][nt][0], acc[mt][nt][1]);
            *(float2*)(Gp + (r + 8) * KC + c) = make_float2(acc[mt][nt][2], acc[mt][nt][3]);
        }
    }
}

// ---------------------------------------------------------------------------
// qform: ssq[b,o,i] = a_i^T G_o a_i;  G = rna(sum of 4 partials) at load time.
// CTA = (i-tile 128, o, b), 256 threads = 8 warps (4m x 2n), warp tile 32x72.
// ---------------------------------------------------------------------------
#define QP 148
#define QA_OFF 512
#define QG_OFF (QA_OFF + 128 * QP * 4)
#define SMEM_QF (QG_OFF + KC * QP * 4)     // 161536

__global__ __launch_bounds__(256, 1) void qform_kernel()
{
    extern __shared__ __align__(16) char smq[];
    float* s_q = (float*)smq;                 // [128]
    float* As = (float*)(smq + QA_OFF);
    float* Gs = (float*)(smq + QG_OFF);

    const int tid = threadIdx.x;
    const int wid = tid >> 5;
    const int lane = tid & 31;
    const int gid = lane >> 2;
    const int tg = lane & 3;
    const int wm = wid & 3;
    const int wn = wid >> 2;
    const int ibase = blockIdx.x * 128;
    const int o = blockIdx.y;
    const int b = blockIdx.z;

    const float* Ab = g_Ag + ((size_t)b * HS + ibase) * KC;
    const size_t gstride = (size_t)Bn * On * KC * KC;
    const float* Gp0 = g_Gp + (size_t)(b * On + o) * KC * KC;

    if (tid < 128) s_q[tid] = 0.f;
    for (int l = tid; l < 128 * 36; l += 256) {
        int r = l / 36, k4 = l - r * 36;
        *(float4*)(As + r * QP + k4 * 4) = *(const float4*)(Ab + (size_t)r * KC + k4 * 4);
    }
    for (int l = tid; l < KC * 36; l += 256) {
        int r = l / 36, k4 = l - r * 36;
        size_t off = (size_t)r * KC + k4 * 4;
        float4 v0 = *(const float4*)(Gp0 + off);
        float4 v1 = *(const float4*)(Gp0 + gstride + off);
        float4 v2 = *(const float4*)(Gp0 + 2 * gstride + off);
        float4 v3 = *(const float4*)(Gp0 + 3 * gstride + off);
        float4 v = make_float4((v0.x + v1.x) + (v2.x + v3.x),
                               (v0.y + v1.y) + (v2.y + v3.y),
                               (v0.z + v1.z) + (v2.z + v3.z),
                               (v0.w + v1.w) + (v2.w + v3.w));
        asm("cvt.rna.tf32.f32 %0, %0;" : "+f"(v.x));
        asm("cvt.rna.tf32.f32 %0, %0;" : "+f"(v.y));
        asm("cvt.rna.tf32.f32 %0, %0;" : "+f"(v.z));
        asm("cvt.rna.tf32.f32 %0, %0;" : "+f"(v.w));
        *(float4*)(Gs + r * QP + k4 * 4) = v;
    }
    __syncthreads();

    float acc[2][9][4] = {};
    #pragma unroll
    for (int ks = 0; ks < NK; ++ks) {
        int kp = ks * 8 + tg * 2;
        float2 af[2][2];
        #pragma unroll
        for (int mt = 0; mt < 2; ++mt) {
            int r = wm * 32 + mt * 16 + gid;
            af[mt][0] = *(const float2*)(As + r * QP + kp);
            af[mt][1] = *(const float2*)(As + (r + 8) * QP + kp);
        }
        #pragma unroll
        for (int nt = 0; nt < 9; ++nt) {
            int n = wn * 72 + nt * 8 + gid;
            float2 bv = *(const float2*)(Gs + n * QP + kp);
            #pragma unroll
            for (int mt = 0; mt < 2; ++mt)
                mma_tf32(acc[mt][nt],
                         __float_as_uint(af[mt][0].x), __float_as_uint(af[mt][1].x),
                         __float_as_uint(af[mt][0].y), __float_as_uint(af[mt][1].y),
                         __float_as_uint(bv.x), __float_as_uint(bv.y));
        }
    }

    #pragma unroll
    for (int mt = 0; mt < 2; ++mt) {
        int r = wm * 32 + mt * 16 + gid;
        float lo = 0.f, hi = 0.f;
        #pragma unroll
        for (int nt = 0; nt < 9; ++nt) {
            int c = wn * 72 + nt * 8 + tg * 2;
            lo += acc[mt][nt][0] * As[r * QP + c] + acc[mt][nt][1] * As[r * QP + c + 1];
            hi += acc[mt][nt][2] * As[(r + 8) * QP + c] + acc[mt][nt][3] * As[(r + 8) * QP + c + 1];
        }
        lo += __shfl_xor_sync(0xffffffffu, lo, 1);
        lo += __shfl_xor_sync(0xffffffffu, lo, 2);
        hi += __shfl_xor_sync(0xffffffffu, hi, 1);
        hi += __shfl_xor_sync(0xffffffffu, hi, 2);
        if (tg == 0) {
            atomicAdd(&s_q[r], lo);
            atomicAdd(&s_q[r + 8], hi);
        }
    }
    __syncthreads();
    if (tid < 128)
        g_scale[(size_t)(b * On + o) * HS + ibase + tid] =
            1.f / fmaxf(sqrtf(s_q[tid]), 1e-12f);
}

// ---------------------------------------------------------------------------
// big_mma: cofe GEMM, single pass, pre-scaled write, cp.async 2-stage B pipe.
// CTA = (i-tile 256, o, b), 512 threads = 16 warps (4m x 4n), warp tile 64x16.
// 16 j-tiles of 64; B stage fills fly under previous tile's MMAs + stores.
// ---------------------------------------------------------------------------
#define LDPA 152
#define LDPB 148
#define A_OFF 0
#define B_OFF (256 * LDPA * 4)                  // 155648
#define BSTG (64 * LDPB * 4)                    // 37888 per stage
#define SMEM_MMA (B_OFF + 2 * BSTG)             // 231424

__global__ __launch_bounds__(512, 1) void big_mma(float* __restrict__ out)
{
    extern __shared__ __align__(16) char sm[];
    float* As = (float*)(sm + A_OFF);
    const uint32_t b_smem = smem_u32(sm) + B_OFF;

    const int tid = threadIdx.x;
    const int wid = tid >> 5;
    const int lane = tid & 31;
    const int gid = lane >> 2;
    const int tg = lane & 3;
    const int wm = wid & 3;                 // 4 m-bands of 64 rows
    const int wn = wid >> 2;                // 4 n-bands of 16 cols

    const int ibase = blockIdx.x * 256;
    const int o = blockIdx.y;
    const int b = blockIdx.z;

    const float* Ab = g_Ag + ((size_t)b * HS + ibase) * KC;
    const float* Bb = g_Bg + ((size_t)(b * On + o) * HS) * KC;
    float* outBO = out + (size_t)(b * On + o) * HS * HS;

    // per-thread row scales (8 rows/thread)
    float sc[4][2];
    {
        const float* scp = g_scale + (size_t)(b * On + o) * HS + ibase;
        #pragma unroll
        for (int mt = 0; mt < 4; ++mt) {
            int r = wm * 64 + mt * 16 + gid;
            sc[mt][0] = scp[r];
            sc[mt][1] = scp[r + 8];
        }
    }

    // B stage fill via cp.async: 64 rows x 36 float4 = 2304 float4
    auto fill_B = [&](int stage, int jt) {
        const float* Bt = Bb + (size_t)(jt * 64) * KC;
        uint32_t dst_base = b_smem + stage * BSTG;
        for (int l = tid; l < 64 * 36; l += 512) {
            int r = l / 36, k4 = l - r * 36;
            cp_async16(dst_base + (r * LDPB + k4 * 4) * 4,
                       Bt + (size_t)r * KC + k4 * 4);
        }
        CP_COMMIT();
    };

    // prologue: stages for jt 0 and 1 in flight; A tile filled meanwhile
    fill_B(0, 0);
    fill_B(1, 1);
    for (int l = tid; l < 256 * 36; l += 512) {
        int r = l / 36, k4 = l - r * 36;
        *(float4*)(As + r * LDPA + k4 * 4) = *(const float4*)(Ab + (size_t)r * KC + k4 * 4);
    }

    const float* Apt[4];
    #pragma unroll
    for (int mt = 0; mt < 4; ++mt)
        Apt[mt] = As + (wm * 64 + mt * 16 + gid) * LDPA + tg * 2;

    #pragma unroll 1
    for (int jt = 0; jt < 16; ++jt) {
        if (jt < 15) { CP_WAIT(1); } else { CP_WAIT(0); }
        __syncthreads();   // stage (jt&1) data visible to all; prior readers done

        const float* Bst = (const float*)(sm + B_OFF + (jt & 1) * BSTG);
        const float* Bpt[2];
        #pragma unroll
        for (int nt = 0; nt < 2; ++nt)
            Bpt[nt] = Bst + (wn * 16 + nt * 8 + gid) * LDPB + tg * 2;

        float acc[4][2][4] = {};
        #pragma unroll
        for (int ks = 0; ks < NK; ++ks) {
            float2 af[4][2], bf[2];
            #pragma unroll
            for (int mt = 0; mt < 4; ++mt) {
                af[mt][0] = *(const float2*)(Apt[mt] + ks * 8);
                af[mt][1] = *(const float2*)(Apt[mt] + ks * 8 + 8 * LDPA);
            }
            #pragma unroll
            for (int nt = 0; nt < 2; ++nt)
                bf[nt] = *(const float2*)(Bpt[nt] + ks * 8);
            #pragma unroll
            for (int mt = 0; mt < 4; ++mt)
                #pragma unroll
                for (int nt = 0; nt < 2; ++nt)
                    mma_tf32(acc[mt][nt],
                             __float_as_uint(af[mt][0].x), __float_as_uint(af[mt][1].x),
                             __float_as_uint(af[mt][0].y), __float_as_uint(af[mt][1].y),
                             __float_as_uint(bf[nt].x), __float_as_uint(bf[nt].y));
        }

        __syncthreads();   // all warps done reading stage (jt&1)
        if (jt + 2 < 16) fill_B(jt & 1, jt + 2);   // refill flies under stores

        // Write scaled output for this j-tile
        #pragma unroll
        for (int mt = 0; mt < 4; ++mt) {
            int r0 = ibase + wm * 64 + mt * 16 + gid;
            float s0 = sc[mt][0], s1 = sc[mt][1];
            #pragma unroll
            for (int nt = 0; nt < 2; ++nt) {
                int c = jt * 64 + wn * 16 + nt * 8 + tg * 2;
                *(float2*)(outBO + (size_t)r0 * HS + c) =
                    make_float2(acc[mt][nt][0] * s0, acc[mt][nt][1] * s0);
                *(float2*)(outBO + (size_t)(r0 + 8) * HS + c) =
                    make_float2(acc[mt][nt][2] * s1, acc[mt][nt][3] * s1);
            }
        }
    }
}

// ---------------------------------------------------------------------------
extern "C" void kernel_launch(void* const* d_in, const int* in_sizes, int n_in,
                              void* d_out, int out_size)
{
    const float* x  = (const float*)d_in[0];
    const float* w1 = (const float*)d_in[1];
    const float* b1 = (const float*)d_in[2];
    const float* w2 = (const float*)d_in[3];
    const float* b2 = (const float*)d_in[4];
    float* out = (float*)d_out;

    cudaFuncSetAttribute(big_mma, cudaFuncAttributeMaxDynamicSharedMemorySize, SMEM_MMA);
    cudaFuncSetAttribute(qform_kernel, cudaFuncAttributeMaxDynamicSharedMemorySize, SMEM_QF);
    cudaFuncSetAttribute(gram_kernel, cudaFuncAttributeMaxDynamicSharedMemorySize, SMEM_GRAM);

    dim3 tpb(256);
    proj_kernel<<<dim3(7, 16, Bn), tpb>>>(x, w1, b1, 0);
    proj_kernel<<<dim3(7, 16, Bn), tpb>>>(x, w2, b2, 1);
    gather_kernel<<<Bn * HS + Bn * On * HS, 160>>>();
    gram_kernel<<<dim3(On, Bn, 4), 288, SMEM_GRAM>>>();
    qform_kernel<<<dim3(8, On, Bn), 256, SMEM_QF>>>();
    big_mma<<<dim3(HS / 256, On, Bn), dim3(512), SMEM_MMA>>>(out);
}

// round 17
// speedup vs baseline: 1.0791x; 1.0791x over previous
#include <cuda_runtime.h>
#include <cstdint>

// Problem constants
#define Bn 8
#define Cc 512
#define Ww 14
#define HS 1024
#define Sp 196      // 14*14
#define KC 144      // 12*12 interior centers
#define On 9        // 3x3 offsets
#define NK 18       // 144 / 8 k-steps

// Scratch (__device__ globals: allocation-free rule)
__device__ float g_P1[Bn * HS * Sp];
__device__ float g_P2[Bn * HS * Sp];
__device__ float g_Ag[(size_t)Bn * HS * KC];          // gathered, tf32-rounded, k-permuted
__device__ float g_Bg[(size_t)Bn * On * HS * KC];     // gathered, tf32-rounded, k-permuted
__device__ float g_Gp[2 * (size_t)Bn * On * KC * KC]; // partial Gram matrices (2 j-halves)
__device__ float g_scale[(size_t)Bn * On * HS];       // per-row 1/max(||row||,eps)

__device__ __forceinline__ void mma_tf32(float* c, uint32_t a0, uint32_t a1,
                                         uint32_t a2, uint32_t a3,
                                         uint32_t b0, uint32_t b1) {
    asm volatile(
        "mma.sync.aligned.m16n8k8.row.col.f32.tf32.tf32.f32 "
        "{%0,%1,%2,%3}, {%4,%5,%6,%7}, {%8,%9}, {%0,%1,%2,%3};"
        : "+f"(c[0]), "+f"(c[1]), "+f"(c[2]), "+f"(c[3])
        : "r"(a0), "r"(a1), "r"(a2), "r"(a3), "r"(b0), "r"(b1));
}

// ---------------------------------------------------------------------------
// proj: P[b][h][s] = sum_c w[h][c] * x[b][c][s] + bias[h]   (unchanged, passing)
// ---------------------------------------------------------------------------
__global__ __launch_bounds__(256) void proj_kernel(const float* __restrict__ x,
                                                   const float* __restrict__ w,
                                                   const float* __restrict__ bias,
                                                   int which)
{
    __shared__ __align__(16) float Wst[32 * 68];
    __shared__ __align__(16) float Xs[32 * 33];

    float* outP = which ? g_P2 : g_P1;
    const int tid = threadIdx.x;
    const int tx = tid & 15;
    const int ty = tid >> 4;
    const int sbase = blockIdx.x * 32;
    const int hbase = blockIdx.y * 64;
    const int b = blockIdx.z;

    float acc[4][2] = {};
    for (int cb = 0; cb < Cc; cb += 32) {
        #pragma unroll
        for (int r = 0; r < 8; ++r) {
            int l = tid + r * 256;
            int h = l >> 5, c = l & 31;
            Wst[c * 68 + h] = w[(hbase + h) * Cc + cb + c];
        }
        #pragma unroll
        for (int r = 0; r < 4; ++r) {
            int l = tid + r * 256;
            int c = l >> 5, s = l & 31;
            int sg = sbase + s;
            Xs[c * 33 + s] = (sg < Sp) ? x[(b * Cc + cb + c) * Sp + sg] : 0.f;
        }
        __syncthreads();
        #pragma unroll 8
        for (int c = 0; c < 32; ++c) {
            float4 a = *(const float4*)(Wst + c * 68 + ty * 4);
            float b0 = Xs[c * 33 + tx * 2];
            float b1 = Xs[c * 33 + tx * 2 + 1];
            acc[0][0] += a.x * b0; acc[0][1] += a.x * b1;
            acc[1][0] += a.y * b0; acc[1][1] += a.y * b1;
            acc[2][0] += a.z * b0; acc[2][1] += a.z * b1;
            acc[3][0] += a.w * b0; acc[3][1] += a.w * b1;
        }
        __syncthreads();
    }
    #pragma unroll
    for (int u = 0; u < 4; ++u) {
        int h = hbase + ty * 4 + u;
        float bb = bias[h];
        #pragma unroll
        for (int v = 0; v < 2; ++v) {
            int s = sbase + tx * 2 + v;
            if (s < Sp) outP[(b * HS + h) * Sp + s] = acc[u][v] + bb;
        }
    }
}

// ---------------------------------------------------------------------------
// gather: gathered operands, tf32-rounded, k-chunk permuted [0,4,1,5,2,6,3,7]
// ---------------------------------------------------------------------------
__global__ __launch_bounds__(160) void gather_kernel()
{
    int row = blockIdx.x;
    int k = threadIdx.x;
    if (k >= KC) return;
    int ky = k / 12, kx = k - ky * 12;
    int ks = k >> 3, kk = k & 7;
    int dpos = ks * 8 + (kk & 3) * 2 + (kk >> 2);
    float v;
    if (row < Bn * HS) {
        int s = (1 + ky) * Ww + 1 + kx;
        v = g_P1[(size_t)row * Sp + s];
        asm("cvt.rna.tf32.f32 %0, %0;" : "+f"(v));
        g_Ag[(size_t)row * KC + dpos] = v;
    } else {
        int r2 = row - Bn * HS;
        int b = r2 / (On * HS);
        int rem = r2 - b * On * HS;
        int o = rem >> 10;
        int j = rem & 1023;
        int delta = (o / 3 - 1) * Ww + (o % 3 - 1);
        int s = (1 + ky) * Ww + 1 + kx + delta;
        v = g_P2[((size_t)b * HS + j) * Sp + s];
        asm("cvt.rna.tf32.f32 %0, %0;" : "+f"(v));
        g_Bg[(size_t)r2 * KC + dpos] = v;
    }
}

// ---------------------------------------------------------------------------
// gram: partial Gram G_half = Bg_half^T Bg_half (144x144), per (b,o,half).
// CTA = (o, b, half), 288 threads = 9 warps (3m x 3n), warp tile 48x48.
// Each half covers 512 j in 8 chunks of 64, double-buffered (LDG under MMA).
// ---------------------------------------------------------------------------
#define TP 65
#define TBUF (KC * TP)
#define SMEM_GRAM (2 * TBUF * 4)   // 74880

__global__ __launch_bounds__(288, 1) void gram_kernel()
{
    extern __shared__ __align__(16) float T[];   // [2][KC*TP]

    const int tid = threadIdx.x;
    const int wid = tid >> 5;
    const int lane = tid & 31;
    const int gid = lane >> 2;
    const int tg = lane & 3;
    const int wm = wid / 3;
    const int wn = wid % 3;
    const int o = blockIdx.x;
    const int b = blockIdx.y;
    const int half = blockIdx.z;

    const float* Bb = g_Bg + ((size_t)(b * On + o) * HS + half * 512) * KC;

    int lj[8], lk4[8];
    #pragma unroll
    for (int r = 0; r < 8; ++r) {
        int l = tid + r * 288;
        lj[r] = l / 36;
        lk4[r] = l - lj[r] * 36;
    }

    float4 ld[8];
    #pragma unroll
    for (int r = 0; r < 8; ++r)
        ld[r] = *(const float4*)(Bb + (size_t)lj[r] * KC + lk4[r] * 4);
    #pragma unroll
    for (int r = 0; r < 8; ++r) {
        T[(4 * lk4[r] + 0) * TP + lj[r]] = ld[r].x;
        T[(4 * lk4[r] + 1) * TP + lj[r]] = ld[r].y;
        T[(4 * lk4[r] + 2) * TP + lj[r]] = ld[r].z;
        T[(4 * lk4[r] + 3) * TP + lj[r]] = ld[r].w;
    }
    __syncthreads();

    float acc[3][6][4] = {};

    for (int jc = 0; jc < 8; ++jc) {
        const float* cur = T + (jc & 1) * TBUF;
        float* nxt = T + ((jc & 1) ^ 1) * TBUF;

        if (jc < 7) {
            const float* Bc = Bb + (size_t)(jc + 1) * 64 * KC;
            #pragma unroll
            for (int r = 0; r < 8; ++r)
                ld[r] = *(const float4*)(Bc + (size_t)lj[r] * KC + lk4[r] * 4);
        }

        #pragma unroll
        for (int js = 0; js < 8; ++js) {
            int j0 = js * 8 + tg;
            uint32_t af[3][4], bf[6][2];
            #pragma unroll
            for (int mt = 0; mt < 3; ++mt) {
                int m = wm * 48 + mt * 16 + gid;
                af[mt][0] = __float_as_uint(cur[m * TP + j0]);
                af[mt][1] = __float_as_uint(cur[(m + 8) * TP + j0]);
                af[mt][2] = __float_as_uint(cur[m * TP + j0 + 4]);
                af[mt][3] = __float_as_uint(cur[(m + 8) * TP + j0 + 4]);
            }
            #pragma unroll
            for (int nt = 0; nt < 6; ++nt) {
                int n = wn * 48 + nt * 8 + gid;
                bf[nt][0] = __float_as_uint(cur[n * TP + j0]);
                bf[nt][1] = __float_as_uint(cur[n * TP + j0 + 4]);
            }
            #pragma unroll
            for (int mt = 0; mt < 3; ++mt)
                #pragma unroll
                for (int nt = 0; nt < 6; ++nt)
                    mma_tf32(acc[mt][nt], af[mt][0], af[mt][1], af[mt][2], af[mt][3],
                             bf[nt][0], bf[nt][1]);
        }

        if (jc < 7) {
            #pragma unroll
            for (int r = 0; r < 8; ++r) {
                nxt[(4 * lk4[r] + 0) * TP + lj[r]] = ld[r].x;
                nxt[(4 * lk4[r] + 1) * TP + lj[r]] = ld[r].y;
                nxt[(4 * lk4[r] + 2) * TP + lj[r]] = ld[r].z;
                nxt[(4 * lk4[r] + 3) * TP + lj[r]] = ld[r].w;
            }
        }
        __syncthreads();
    }

    float* Gp = g_Gp + ((size_t)half * Bn * On + (size_t)(b * On + o)) * KC * KC;
    #pragma unroll
    for (int mt = 0; mt < 3; ++mt) {
        int r = wm * 48 + mt * 16 + gid;
        #pragma unroll
        for (int nt = 0; nt < 6; ++nt) {
            int c = wn * 48 + nt * 8 + tg * 2;
            *(float2*)(Gp + r * KC + c) = make_float2(acc[mt][nt][0], acc[mt][nt][1]);
            *(float2*)(Gp + (r + 8) * KC + c) = make_float2(acc[mt][nt][2], acc[mt][nt][3]);
        }
    }
}

// ---------------------------------------------------------------------------
// qform: ssq[b,o,i] = a_i^T G_o a_i;  G = rna(Gp[0] + Gp[1]) at load time.
// CTA = (i-tile 128, o, b), 256 threads = 8 warps (4m x 2n), warp tile 32x72.
// ---------------------------------------------------------------------------
#define QP 148
#define QA_OFF 512
#define QG_OFF (QA_OFF + 128 * QP * 4)
#define SMEM_QF (QG_OFF + KC * QP * 4)     // 161536

__global__ __launch_bounds__(256, 1) void qform_kernel()
{
    extern __shared__ __align__(16) char smq[];
    float* s_q = (float*)smq;                 // [128]
    float* As = (float*)(smq + QA_OFF);
    float* Gs = (float*)(smq + QG_OFF);

    const int tid = threadIdx.x;
    const int wid = tid >> 5;
    const int lane = tid & 31;
    const int gid = lane >> 2;
    const int tg = lane & 3;
    const int wm = wid & 3;
    const int wn = wid >> 2;
    const int ibase = blockIdx.x * 128;
    const int o = blockIdx.y;
    const int b = blockIdx.z;

    const float* Ab = g_Ag + ((size_t)b * HS + ibase) * KC;
    const float* Gp0 = g_Gp + (size_t)(b * On + o) * KC * KC;
    const float* Gp1 = Gp0 + (size_t)Bn * On * KC * KC;

    if (tid < 128) s_q[tid] = 0.f;
    for (int l = tid; l < 128 * 36; l += 256) {
        int r = l / 36, k4 = l - r * 36;
        *(float4*)(As + r * QP + k4 * 4) = *(const float4*)(Ab + (size_t)r * KC + k4 * 4);
    }
    for (int l = tid; l < KC * 36; l += 256) {
        int r = l / 36, k4 = l - r * 36;
        size_t off = (size_t)r * KC + k4 * 4;
        float4 v0 = *(const float4*)(Gp0 + off);
        float4 v1 = *(const float4*)(Gp1 + off);
        float4 v = make_float4(v0.x + v1.x, v0.y + v1.y, v0.z + v1.z, v0.w + v1.w);
        asm("cvt.rna.tf32.f32 %0, %0;" : "+f"(v.x));
        asm("cvt.rna.tf32.f32 %0, %0;" : "+f"(v.y));
        asm("cvt.rna.tf32.f32 %0, %0;" : "+f"(v.z));
        asm("cvt.rna.tf32.f32 %0, %0;" : "+f"(v.w));
        *(float4*)(Gs + r * QP + k4 * 4) = v;
    }
    __syncthreads();

    float acc[2][9][4] = {};
    #pragma unroll
    for (int ks = 0; ks < NK; ++ks) {
        int kp = ks * 8 + tg * 2;
        float2 af[2][2];
        #pragma unroll
        for (int mt = 0; mt < 2; ++mt) {
            int r = wm * 32 + mt * 16 + gid;
            af[mt][0] = *(const float2*)(As + r * QP + kp);
            af[mt][1] = *(const float2*)(As + (r + 8) * QP + kp);
        }
        #pragma unroll
        for (int nt = 0; nt < 9; ++nt) {
            int n = wn * 72 + nt * 8 + gid;
            float2 bv = *(const float2*)(Gs + n * QP + kp);
            #pragma unroll
            for (int mt = 0; mt < 2; ++mt)
                mma_tf32(acc[mt][nt],
                         __float_as_uint(af[mt][0].x), __float_as_uint(af[mt][1].x),
                         __float_as_uint(af[mt][0].y), __float_as_uint(af[mt][1].y),
                         __float_as_uint(bv.x), __float_as_uint(bv.y));
        }
    }

    #pragma unroll
    for (int mt = 0; mt < 2; ++mt) {
        int r = wm * 32 + mt * 16 + gid;
        float lo = 0.f, hi = 0.f;
        #pragma unroll
        for (int nt = 0; nt < 9; ++nt) {
            int c = wn * 72 + nt * 8 + tg * 2;
            lo += acc[mt][nt][0] * As[r * QP + c] + acc[mt][nt][1] * As[r * QP + c + 1];
            hi += acc[mt][nt][2] * As[(r + 8) * QP + c] + acc[mt][nt][3] * As[(r + 8) * QP + c + 1];
        }
        lo += __shfl_xor_sync(0xffffffffu, lo, 1);
        lo += __shfl_xor_sync(0xffffffffu, lo, 2);
        hi += __shfl_xor_sync(0xffffffffu, hi, 1);
        hi += __shfl_xor_sync(0xffffffffu, hi, 2);
        if (tg == 0) {
            atomicAdd(&s_q[r], lo);
            atomicAdd(&s_q[r + 8], hi);
        }
    }
    __syncthreads();
    if (tid < 128)
        g_scale[(size_t)(b * On + o) * HS + ibase + tid] =
            1.f / fmaxf(sqrtf(s_q[tid]), 1e-12f);
}

// ---------------------------------------------------------------------------
// big_mma: cofe GEMM, single pass, pre-scaled write. 2 CTAs/SM co-tenancy:
// CTA = (i-tile 128, o, b), 256 threads = 8 warps (4m x 2n), warp tile 32x32.
// j-tile 64 (16 tiles). Pitch 144 with XOR-32B swizzle (k4 ^= ((row>>1)&1)<<1)
// keeps fragment LDS.64 conflict-free; reads use ks ^ ((gid>>1)&1).
// ---------------------------------------------------------------------------
#define LDK 144
#define A_OFF 0
#define B_OFF (128 * LDK * 4)                  // 73728
#define SMEM_MMA (B_OFF + 64 * LDK * 4)        // 110592 -> 2 CTAs/SM

__global__ __launch_bounds__(256, 2) void big_mma(float* __restrict__ out)
{
    extern __shared__ __align__(16) char sm[];
    float* As = (float*)(sm + A_OFF);
    float* Bs = (float*)(sm + B_OFF);

    const int tid = threadIdx.x;
    const int wid = tid >> 5;
    const int lane = tid & 31;
    const int gid = lane >> 2;
    const int tg = lane & 3;
    const int wm = wid & 3;                 // 4 m-bands of 32 rows
    const int wn = wid >> 2;                // 2 n-bands of 32 cols
    const int kx = (gid >> 1) & 1;          // per-lane k-step swizzle compensation

    const int ibase = blockIdx.x * 128;
    const int o = blockIdx.y;
    const int b = blockIdx.z;

    const float* Ab = g_Ag + ((size_t)b * HS + ibase) * KC;
    const float* Bb = g_Bg + ((size_t)(b * On + o) * HS) * KC;
    float* outBO = out + (size_t)(b * On + o) * HS * HS;

    // per-thread row scales (4 rows/thread)
    float sc[2][2];
    {
        const float* scp = g_scale + (size_t)(b * On + o) * HS + ibase;
        #pragma unroll
        for (int mt = 0; mt < 2; ++mt) {
            int r = wm * 32 + mt * 16 + gid;
            sc[mt][0] = scp[r];
            sc[mt][1] = scp[r + 8];
        }
    }

    // Fill A tile: 128 rows x 36 float4, swizzled (flip k4 bit1 on odd row-pairs)
    for (int l = tid; l < 128 * 36; l += 256) {
        int r = l / 36, k4 = l - r * 36;
        int k4s = k4 ^ (((r >> 1) & 1) << 1);
        *(float4*)(As + r * LDK + k4s * 4) = *(const float4*)(Ab + (size_t)r * KC + k4 * 4);
    }

    // Fragment base pointers (swizzle handled via kx at read time)
    const float* Apt[2];
    #pragma unroll
    for (int mt = 0; mt < 2; ++mt)
        Apt[mt] = As + (wm * 32 + mt * 16 + gid) * LDK + tg * 2;
    const float* Bpt[4];
    #pragma unroll
    for (int nt = 0; nt < 4; ++nt)
        Bpt[nt] = Bs + (wn * 32 + nt * 8 + gid) * LDK + tg * 2;

    #pragma unroll 1
    for (int jt = 0; jt < 16; ++jt) {
        __syncthreads();                // Bs free (A visible on iter 0)
        const float* Bt = Bb + (size_t)(jt * 64) * KC;
        for (int l = tid; l < 64 * 36; l += 256) {
            int r = l / 36, k4 = l - r * 36;
            int k4s = k4 ^ (((r >> 1) & 1) << 1);
            *(float4*)(Bs + r * LDK + k4s * 4) = *(const float4*)(Bt + (size_t)r * KC + k4 * 4);
        }
        __syncthreads();

        float acc[2][4][4] = {};
        #pragma unroll
        for (int ks = 0; ks < NK; ++ks) {
            const int kofs = (ks ^ kx) * 8;
            float2 af[2][2], bf[4];
            #pragma unroll
            for (int mt = 0; mt < 2; ++mt) {
                af[mt][0] = *(const float2*)(Apt[mt] + kofs);
                af[mt][1] = *(const float2*)(Apt[mt] + kofs + 8 * LDK);
            }
            #pragma unroll
            for (int nt = 0; nt < 4; ++nt)
                bf[nt] = *(const float2*)(Bpt[nt] + kofs);
            #pragma unroll
            for (int mt = 0; mt < 2; ++mt)
                #pragma unroll
                for (int nt = 0; nt < 4; ++nt)
                    mma_tf32(acc[mt][nt],
                             __float_as_uint(af[mt][0].x), __float_as_uint(af[mt][1].x),
                             __float_as_uint(af[mt][0].y), __float_as_uint(af[mt][1].y),
                             __float_as_uint(bf[nt].x), __float_as_uint(bf[nt].y));
        }

        // Write scaled output for this j-tile
        #pragma unroll
        for (int mt = 0; mt < 2; ++mt) {
            int r0 = ibase + wm * 32 + mt * 16 + gid;
            float s0 = sc[mt][0], s1 = sc[mt][1];
            #pragma unroll
            for (int nt = 0; nt < 4; ++nt) {
                int c = jt * 64 + wn * 32 + nt * 8 + tg * 2;
                *(float2*)(outBO + (size_t)r0 * HS + c) =
                    make_float2(acc[mt][nt][0] * s0, acc[mt][nt][1] * s0);
                *(float2*)(outBO + (size_t)(r0 + 8) * HS + c) =
                    make_float2(acc[mt][nt][2] * s1, acc[mt][nt][3] * s1);
            }
        }
    }
}

// ---------------------------------------------------------------------------
extern "C" void kernel_launch(void* const* d_in, const int* in_sizes, int n_in,
                              void* d_out, int out_size)
{
    const float* x  = (const float*)d_in[0];
    const float* w1 = (const float*)d_in[1];
    const float* b1 = (const float*)d_in[2];
    const float* w2 = (const float*)d_in[3];
    const float* b2 = (const float*)d_in[4];
    float* out = (float*)d_out;

    cudaFuncSetAttribute(big_mma, cudaFuncAttributeMaxDynamicSharedMemorySize, SMEM_MMA);
    cudaFuncSetAttribute(qform_kernel, cudaFuncAttributeMaxDynamicSharedMemorySize, SMEM_QF);
    cudaFuncSetAttribute(gram_kernel, cudaFuncAttributeMaxDynamicSharedMemorySize, SMEM_GRAM);

    dim3 tpb(256);
    proj_kernel<<<dim3(7, 16, Bn), tpb>>>(x, w1, b1, 0);
    proj_kernel<<<dim3(7, 16, Bn), tpb>>>(x, w2, b2, 1);
    gather_kernel<<<Bn * HS + Bn * On * HS, 160>>>();
    gram_kernel<<<dim3(On, Bn, 2), 288, SMEM_GRAM>>>();
    qform_kernel<<<dim3(8, On, Bn), 256, SMEM_QF>>>();
    big_mma<<<dim3(HS / 128, On, Bn), 256, SMEM_MMA>>>(out);
}